// round 16
// baseline (speedup 1.0000x reference)
#include <cuda_runtime.h>
#include <cstdint>

#define NQ 32
#define NS 25
#define NL 64
#define NF 256
#define NH 64
#define NT (NQ * NS)         // 800 (q, s) tiles
#define XSP 260              // proj xs row stride (pad 4)
#define ATS 68               // att row stride (banks 4*gid+tig: conflict-free frags)
#define HSS 72               // hsq row stride (banks 8*tig+gid: conflict-free frags)

// Scratch (allocation-free rule: __device__ globals)
__device__ float g_WqT[NQ * NH * NL];    // per q: [h][i]
__device__ float g_WhT[NS * NH * NL];    // per s: [h][j]
__device__ float g_hsT32[NS * NL * NF];  // hs pre-rounded to tf32
__device__ unsigned g_ticket;

__device__ __forceinline__ float fast_ex2(float x) {
    float r; asm("ex2.approx.f32 %0, %1;" : "=f"(r) : "f"(x)); return r;
}
__device__ __forceinline__ float fast_rcp(float x) {
    float r; asm("rcp.approx.f32 %0, %1;" : "=f"(r) : "f"(x)); return r;
}
__device__ __forceinline__ float fast_tanh(float x) {
    float r; asm("tanh.approx.f32 %0, %1;" : "=f"(r) : "f"(x)); return r;
}
__device__ __forceinline__ unsigned cvt_tf32(float x) {
    unsigned r; asm("cvt.rna.tf32.f32 %0, %1;" : "=r"(r) : "f"(x)); return r;
}
// D(16x8,f32) += A(16x8,tf32,row) * B(8x8,tf32,col)
__device__ __forceinline__ void mma_tf32(float* d,
                                         unsigned a0, unsigned a1, unsigned a2, unsigned a3,
                                         unsigned b0, unsigned b1) {
    asm volatile(
        "mma.sync.aligned.m16n8k8.row.col.f32.tf32.tf32.f32 "
        "{%0,%1,%2,%3}, {%4,%5,%6,%7}, {%8,%9}, {%0,%1,%2,%3};"
        : "+f"(d[0]), "+f"(d[1]), "+f"(d[2]), "+f"(d[3])
        : "r"(a0), "r"(a1), "r"(a2), "r"(a3), "r"(b0), "r"(b1));
}

#define LOG2E 1.4426950408889634f

// K1: projection (+ ticket reset + hs->tf32 pre-round).
__global__ __launch_bounds__(256) void k_project(const float* __restrict__ qs,
                                                 const float* __restrict__ hs,
                                                 const float* __restrict__ W,
                                                 const float* __restrict__ bias) {
    __shared__ float xs[16 * XSP];
    const int b  = blockIdx.x >> 2;
    const int lq = blockIdx.x & 3;
    const int t  = threadIdx.x;

    if (blockIdx.x == 0 && t == 0) g_ticket = 0u;

    // hs -> tf32 (grid-stride; independent of the projection below)
    for (int e = blockIdx.x * 256 + t; e < NS * NL * NF; e += gridDim.x * 256)
        g_hsT32[e] = __uint_as_float(cvt_tf32(__ldg(&hs[e])));

    const float* x = ((b < NQ) ? (qs + (size_t)b * NL * NF)
                               : (hs + (size_t)(b - NQ) * NL * NF))
                     + (size_t)lq * 16 * NF;
    float* dst = (b < NQ) ? (g_WqT + (size_t)b * NH * NL)
                          : (g_WhT + (size_t)(b - NQ) * NH * NL);

    for (int e = t; e < 16 * NF / 4; e += 256) {
        int row = e >> 6;
        int c4 = (e & 63) * 4;
        *reinterpret_cast<float4*>(&xs[row * XSP + c4]) =
            *reinterpret_cast<const float4*>(&x[row * NF + c4]);
    }
    __syncthreads();

    const int h0 = 4 * (t >> 4);
    const int lr = t & 15;
    float acc[4] = {0.f, 0.f, 0.f, 0.f};

    #pragma unroll 2
    for (int f = 0; f < NF; f += 4) {
        float4 xv = *reinterpret_cast<const float4*>(&xs[lr * XSP + f]);
        #pragma unroll
        for (int c = 0; c < 4; c++) {
            float4 w = __ldg(reinterpret_cast<const float4*>(&W[(size_t)(h0 + c) * NF + f]));
            acc[c] = fmaf(w.x, xv.x, fmaf(w.y, xv.y, fmaf(w.z, xv.z, fmaf(w.w, xv.w, acc[c]))));
        }
    }
    const int l = lq * 16 + lr;
    #pragma unroll
    for (int c = 0; c < 4; c++)
        dst[(h0 + c) * NL + l] = acc[c] + __ldg(&bias[h0 + c]);
}

// K2: persistent fused kernel, 800 (q,s) tiles; phase C on tensor cores (tf32)
// with double-buffered hs staging + prefetched ticket.
// ANTI-LOCKSTEP: same-SM CTAs (bid, bid+148, ...) are phase-shifted by
// rank*22K cycles so one CTA's MUFU-bound phase A overlaps another's
// tensor/LDS-bound phase C. MUFU stays fed; injected idle overlaps with
// rank-0's saturated A phase and the shared ticket pool rebalances work.
// smem (floats): phase A: wqT[0..4096); whT[4096..8192)
//   overlay: attH[0..4352)=[64i][ATS]; hsb0[4352..8960); hsb1[8960..13568)
//   ticket slot [13568]. Total 13572 f = 54288 B -> occ 4.
__global__ __launch_bounds__(256, 4) void k_attn(float* __restrict__ out) {
    extern __shared__ float sm[];
    float* wqT = sm;
    float* whT = sm + 4096;
    float* attH = sm;            // overlay: att (tf32-rounded), [i][j] stride ATS
    float* hsb0 = sm + 4352;
    float* hsb1 = sm + 8960;
    float* tslot = sm + 13568;

    const int t = threadIdx.x;
    const int lane = t & 31, w = t >> 5;
    const int gid = lane >> 2, tig = lane & 3;
    const int i0 = 4 * (t >> 4), j0 = 4 * (t & 15);   // phase A tiling
    const int m0 = 16 * (w & 3), nw = 32 * (w >> 2);  // phase C warp tiling

    // de-lockstep: quarter-tile phase shift per same-SM CTA rank
    {
        const int rank = blockIdx.x / 148;             // 0..3 (grid = 148*4)
        const long long wait = (long long)rank * 22000;
        if (wait > 0) {
            long long st = clock64();
            while (clock64() - st < wait) { }
        }
    }

    if (t == 0) tslot[0] = __uint_as_float(atomicAdd(&g_ticket, 1u));
    __syncthreads();

    for (;;) {
        const unsigned T = __float_as_uint(tslot[0]);   // published by prior pass-3 sync
        if (T >= NT) return;
        const int q = (int)T / NS;
        const int s = (int)T % NS;

        {
            const float4* a4 = reinterpret_cast<const float4*>(g_WqT + (size_t)q * NH * NL);
            const float4* b4 = reinterpret_cast<const float4*>(g_WhT + (size_t)s * NH * NL);
            float4* w1 = reinterpret_cast<float4*>(wqT);
            float4* w2 = reinterpret_cast<float4*>(whT);
            for (int e = t; e < NH * NL / 4; e += 256) { w1[e] = a4[e]; w2[e] = b4[e]; }
        }
        __syncthreads();

        // Phase A: acc[r][c] = sum_h tanh(wq[i0+r][h] * wh[j0+c][h])
        float acc[4][4];
        #pragma unroll
        for (int r = 0; r < 4; r++)
            #pragma unroll
            for (int c = 0; c < 4; c++) acc[r][c] = 0.f;

        #pragma unroll 2
        for (int h = 0; h < NH; h++) {
            float4 a4 = *reinterpret_cast<const float4*>(&wqT[h * NL + i0]);
            float4 b4 = *reinterpret_cast<const float4*>(&whT[h * NL + j0]);
            float av[4] = {a4.x, a4.y, a4.z, a4.w};
            float bv[4] = {b4.x, b4.y, b4.z, b4.w};
            #pragma unroll
            for (int r = 0; r < 4; r++)
                #pragma unroll
                for (int c = 0; c < 4; c++)
                    acc[r][c] += fast_tanh(av[r] * bv[c]);
        }

        // Phase B: softmax over j per row.
        float inv[4];
        #pragma unroll
        for (int r = 0; r < 4; r++) {
            float m = fmaxf(fmaxf(acc[r][0], acc[r][1]), fmaxf(acc[r][2], acc[r][3]));
            #pragma unroll
            for (int d = 1; d < 16; d <<= 1)
                m = fmaxf(m, __shfl_xor_sync(0xffffffffu, m, d));
            float e0 = fast_ex2((acc[r][0] - m) * LOG2E);
            float e1 = fast_ex2((acc[r][1] - m) * LOG2E);
            float e2 = fast_ex2((acc[r][2] - m) * LOG2E);
            float e3 = fast_ex2((acc[r][3] - m) * LOG2E);
            acc[r][0] = e0; acc[r][1] = e1; acc[r][2] = e2; acc[r][3] = e3;
            float ssum = (e0 + e1) + (e2 + e3);
            #pragma unroll
            for (int d = 1; d < 16; d <<= 1)
                ssum += __shfl_xor_sync(0xffffffffu, ssum, d);
            inv[r] = fast_rcp(ssum);
        }

        __syncthreads();  // all phase-A smem reads complete before overlay writes

        const float* hbase = g_hsT32 + (size_t)s * NL * NF;

        // Store att tf32-rounded [i][j]; concurrently stage f-chunk 0 into hsb0.
        #pragma unroll
        for (int r = 0; r < 4; r++) {
            float vh[4];
            #pragma unroll
            for (int c = 0; c < 4; c++)
                vh[c] = __uint_as_float(cvt_tf32(acc[r][c] * inv[r]));
            *reinterpret_cast<float4*>(&attH[(i0 + r) * ATS + j0]) =
                make_float4(vh[0], vh[1], vh[2], vh[3]);
        }
        #pragma unroll
        for (int e = t; e < NL * 64 / 4; e += 256) {
            int j = e >> 4;
            int f4 = (e & 15) * 4;
            *reinterpret_cast<float4*>(&hsb0[j * HSS + f4]) =
                __ldg(reinterpret_cast<const float4*>(&hbase[(size_t)j * NF + f4]));
        }
        __syncthreads();   // att + chunk 0 visible

        // Phase C: 4 f-passes; pass p computes from buf (p&1) while staging
        // pass p+1 into buf ((p+1)&1). One sync per pass.
        float* ob = out + (size_t)((q * NS + s) * NL) * NF;

        #pragma unroll
        for (int p = 0; p < 4; p++) {
            float* cur = (p & 1) ? hsb1 : hsb0;
            float* nxt = (p & 1) ? hsb0 : hsb1;

            if (p < 3) {   // stage next chunk (LDG latency hides behind compute below)
                #pragma unroll
                for (int e = t; e < NL * 64 / 4; e += 256) {
                    int j = e >> 4;
                    int f4 = (e & 15) * 4;
                    *reinterpret_cast<float4*>(&nxt[j * HSS + f4]) =
                        __ldg(reinterpret_cast<const float4*>(
                            &hbase[(size_t)j * NF + 64 * (p + 1) + f4]));
                }
            }

            float d[4][4];
            #pragma unroll
            for (int nt = 0; nt < 4; nt++)
                #pragma unroll
                for (int e = 0; e < 4; e++) d[nt][e] = 0.f;

            const float* aH = attH + (size_t)(m0 + gid) * ATS;

            #pragma unroll
            for (int k0 = 0; k0 < NL; k0 += 8) {
                unsigned ah0 = __float_as_uint(aH[k0 + tig]);
                unsigned ah1 = __float_as_uint(aH[8 * ATS + k0 + tig]);
                unsigned ah2 = __float_as_uint(aH[k0 + tig + 4]);
                unsigned ah3 = __float_as_uint(aH[8 * ATS + k0 + tig + 4]);
                const float* hr0 = cur + (size_t)(k0 + tig) * HSS + nw + gid;
                const float* hr1 = cur + (size_t)(k0 + tig + 4) * HSS + nw + gid;
                #pragma unroll
                for (int nt = 0; nt < 4; nt++) {
                    unsigned b0 = __float_as_uint(hr0[8 * nt]);
                    unsigned b1 = __float_as_uint(hr1[8 * nt]);
                    mma_tf32(d[nt], ah0, ah1, ah2, ah3, b0, b1);
                }
            }

            #pragma unroll
            for (int nt = 0; nt < 4; nt++) {
                int col = 64 * p + nw + 8 * nt + 2 * tig;
                *reinterpret_cast<float2*>(&ob[(size_t)(m0 + gid) * NF + col]) =
                    make_float2(d[nt][0], d[nt][1]);
                *reinterpret_cast<float2*>(&ob[(size_t)(m0 + gid + 8) * NF + col]) =
                    make_float2(d[nt][2], d[nt][3]);
            }

            if (p == 3 && t == 0)   // prefetch next ticket; ATOMG hides in pass 3
                tslot[0] = __uint_as_float(atomicAdd(&g_ticket, 1u));
            __syncthreads();   // staging (p+1) visible; cur free; tslot published
        }
    }
}

extern "C" void kernel_launch(void* const* d_in, const int* in_sizes, int n_in,
                              void* d_out, int out_size) {
    const float* qs = (const float*)d_in[0];
    const float* hs = (const float*)d_in[1];
    const float* W  = (const float*)d_in[2];
    const float* b  = (const float*)d_in[3];
    float* out = (float*)d_out;

    const int smem_attn = 13572 * (int)sizeof(float);  // 54288 B -> occ 4
    cudaFuncSetAttribute(k_attn, cudaFuncAttributeMaxDynamicSharedMemorySize, smem_attn);

    k_project<<<(NQ + NS) * 4, 256>>>(qs, hs, W, b);
    k_attn<<<148 * 4, 256, smem_attn>>>(out);
}

// round 17
// speedup vs baseline: 1.0627x; 1.0627x over previous
#include <cuda_runtime.h>
#include <cstdint>

#define NQ 32
#define NS 25
#define NL 64
#define NF 256
#define NH 64
#define NT (NQ * NS)         // 800 (q, s) tiles
#define XSP 260              // proj xs row stride (pad 4)
#define ATS 68               // att row stride (banks 4*gid+tig: conflict-free frags)
#define HSS 72               // hsq row stride (banks 8*tig+gid: conflict-free frags)

// Scratch (allocation-free rule: __device__ globals)
__device__ float g_WqT[NQ * NH * NL];    // per q: [h][i]
__device__ float g_WhT[NS * NH * NL];    // per s: [h][j]
__device__ float g_hsT32[NS * NL * NF];  // hs pre-rounded to tf32
__device__ unsigned g_ticket;

__device__ __forceinline__ float fast_ex2(float x) {
    float r; asm("ex2.approx.f32 %0, %1;" : "=f"(r) : "f"(x)); return r;
}
__device__ __forceinline__ float fast_rcp(float x) {
    float r; asm("rcp.approx.f32 %0, %1;" : "=f"(r) : "f"(x)); return r;
}
__device__ __forceinline__ float fast_tanh(float x) {
    float r; asm("tanh.approx.f32 %0, %1;" : "=f"(r) : "f"(x)); return r;
}
__device__ __forceinline__ unsigned cvt_tf32(float x) {
    unsigned r; asm("cvt.rna.tf32.f32 %0, %1;" : "=r"(r) : "f"(x)); return r;
}
// D(16x8,f32) += A(16x8,tf32,row) * B(8x8,tf32,col)
__device__ __forceinline__ void mma_tf32(float* d,
                                         unsigned a0, unsigned a1, unsigned a2, unsigned a3,
                                         unsigned b0, unsigned b1) {
    asm volatile(
        "mma.sync.aligned.m16n8k8.row.col.f32.tf32.tf32.f32 "
        "{%0,%1,%2,%3}, {%4,%5,%6,%7}, {%8,%9}, {%0,%1,%2,%3};"
        : "+f"(d[0]), "+f"(d[1]), "+f"(d[2]), "+f"(d[3])
        : "r"(a0), "r"(a1), "r"(a2), "r"(a3), "r"(b0), "r"(b1));
}

#define LOG2E 1.4426950408889634f

// K1: projection (+ ticket reset + hs->tf32 pre-round).
// 456 blocks x 128 threads: one block per (sequence b, l-eighth) -> 3.08 even
// waves on 148 SMs (vs 1.54 lumpy waves at 228x256).
__global__ __launch_bounds__(128) void k_project(const float* __restrict__ qs,
                                                 const float* __restrict__ hs,
                                                 const float* __restrict__ W,
                                                 const float* __restrict__ bias) {
    __shared__ float xs[8 * XSP];
    const int b  = blockIdx.x >> 3;
    const int le = blockIdx.x & 7;
    const int t  = threadIdx.x;

    if (blockIdx.x == 0 && t == 0) g_ticket = 0u;

    // hs -> tf32 (grid-stride; independent of the projection below)
    for (int e = blockIdx.x * 128 + t; e < NS * NL * NF; e += gridDim.x * 128)
        g_hsT32[e] = __uint_as_float(cvt_tf32(__ldg(&hs[e])));

    const float* x = ((b < NQ) ? (qs + (size_t)b * NL * NF)
                               : (hs + (size_t)(b - NQ) * NL * NF))
                     + (size_t)le * 8 * NF;
    float* dst = (b < NQ) ? (g_WqT + (size_t)b * NH * NL)
                          : (g_WhT + (size_t)(b - NQ) * NH * NL);

    for (int e = t; e < 8 * NF / 4; e += 128) {
        int row = e >> 6;
        int c4 = (e & 63) * 4;
        *reinterpret_cast<float4*>(&xs[row * XSP + c4]) =
            *reinterpret_cast<const float4*>(&x[row * NF + c4]);
    }
    __syncthreads();

    const int h0 = 4 * (t >> 3);   // W loads shared across 8 lanes
    const int lr = t & 7;
    float acc[4] = {0.f, 0.f, 0.f, 0.f};

    #pragma unroll 2
    for (int f = 0; f < NF; f += 4) {
        float4 xv = *reinterpret_cast<const float4*>(&xs[lr * XSP + f]);
        #pragma unroll
        for (int c = 0; c < 4; c++) {
            float4 w = __ldg(reinterpret_cast<const float4*>(&W[(size_t)(h0 + c) * NF + f]));
            acc[c] = fmaf(w.x, xv.x, fmaf(w.y, xv.y, fmaf(w.z, xv.z, fmaf(w.w, xv.w, acc[c]))));
        }
    }
    const int l = le * 8 + lr;
    #pragma unroll
    for (int c = 0; c < 4; c++)
        dst[(h0 + c) * NL + l] = acc[c] + __ldg(&bias[h0 + c]);
}

// K2: persistent fused kernel, 800 (q,s) tiles; phase C on tensor cores (tf32)
// with double-buffered hs staging + prefetched ticket.
// Grid 444 (3 CTAs/SM): 800/444 = 1.80 tiles/CTA -> wave 2 at 80% load
// (vs 35% at grid 592) -> ~7K cyc/SM less tail idle.
// smem (floats): phase A: wqT[0..4096); whT[4096..8192)
//   overlay: attH[0..4352)=[64i][ATS]; hsb0[4352..8960); hsb1[8960..13568)
//   ticket slot [13568]. Total 13572 f = 54288 B.
__global__ __launch_bounds__(256, 3) void k_attn(float* __restrict__ out) {
    extern __shared__ float sm[];
    float* wqT = sm;
    float* whT = sm + 4096;
    float* attH = sm;            // overlay: att (tf32-rounded), [i][j] stride ATS
    float* hsb0 = sm + 4352;
    float* hsb1 = sm + 8960;
    float* tslot = sm + 13568;

    const int t = threadIdx.x;
    const int lane = t & 31, w = t >> 5;
    const int gid = lane >> 2, tig = lane & 3;
    const int i0 = 4 * (t >> 4), j0 = 4 * (t & 15);   // phase A tiling
    const int m0 = 16 * (w & 3), nw = 32 * (w >> 2);  // phase C warp tiling

    if (t == 0) tslot[0] = __uint_as_float(atomicAdd(&g_ticket, 1u));
    __syncthreads();

    for (;;) {
        const unsigned T = __float_as_uint(tslot[0]);   // published by prior pass-3 sync
        if (T >= NT) return;
        const int q = (int)T / NS;
        const int s = (int)T % NS;

        {
            const float4* a4 = reinterpret_cast<const float4*>(g_WqT + (size_t)q * NH * NL);
            const float4* b4 = reinterpret_cast<const float4*>(g_WhT + (size_t)s * NH * NL);
            float4* w1 = reinterpret_cast<float4*>(wqT);
            float4* w2 = reinterpret_cast<float4*>(whT);
            for (int e = t; e < NH * NL / 4; e += 256) { w1[e] = a4[e]; w2[e] = b4[e]; }
        }
        __syncthreads();

        // Phase A: acc[r][c] = sum_h tanh(wq[i0+r][h] * wh[j0+c][h])
        float acc[4][4];
        #pragma unroll
        for (int r = 0; r < 4; r++)
            #pragma unroll
            for (int c = 0; c < 4; c++) acc[r][c] = 0.f;

        #pragma unroll 2
        for (int h = 0; h < NH; h++) {
            float4 a4 = *reinterpret_cast<const float4*>(&wqT[h * NL + i0]);
            float4 b4 = *reinterpret_cast<const float4*>(&whT[h * NL + j0]);
            float av[4] = {a4.x, a4.y, a4.z, a4.w};
            float bv[4] = {b4.x, b4.y, b4.z, b4.w};
            #pragma unroll
            for (int r = 0; r < 4; r++)
                #pragma unroll
                for (int c = 0; c < 4; c++)
                    acc[r][c] += fast_tanh(av[r] * bv[c]);
        }

        // Phase B: softmax over j per row.
        float inv[4];
        #pragma unroll
        for (int r = 0; r < 4; r++) {
            float m = fmaxf(fmaxf(acc[r][0], acc[r][1]), fmaxf(acc[r][2], acc[r][3]));
            #pragma unroll
            for (int d = 1; d < 16; d <<= 1)
                m = fmaxf(m, __shfl_xor_sync(0xffffffffu, m, d));
            float e0 = fast_ex2((acc[r][0] - m) * LOG2E);
            float e1 = fast_ex2((acc[r][1] - m) * LOG2E);
            float e2 = fast_ex2((acc[r][2] - m) * LOG2E);
            float e3 = fast_ex2((acc[r][3] - m) * LOG2E);
            acc[r][0] = e0; acc[r][1] = e1; acc[r][2] = e2; acc[r][3] = e3;
            float ssum = (e0 + e1) + (e2 + e3);
            #pragma unroll
            for (int d = 1; d < 16; d <<= 1)
                ssum += __shfl_xor_sync(0xffffffffu, ssum, d);
            inv[r] = fast_rcp(ssum);
        }

        __syncthreads();  // all phase-A smem reads complete before overlay writes

        const float* hbase = g_hsT32 + (size_t)s * NL * NF;

        // Store att tf32-rounded [i][j]; concurrently stage f-chunk 0 into hsb0.
        #pragma unroll
        for (int r = 0; r < 4; r++) {
            float vh[4];
            #pragma unroll
            for (int c = 0; c < 4; c++)
                vh[c] = __uint_as_float(cvt_tf32(acc[r][c] * inv[r]));
            *reinterpret_cast<float4*>(&attH[(i0 + r) * ATS + j0]) =
                make_float4(vh[0], vh[1], vh[2], vh[3]);
        }
        #pragma unroll
        for (int e = t; e < NL * 64 / 4; e += 256) {
            int j = e >> 4;
            int f4 = (e & 15) * 4;
            *reinterpret_cast<float4*>(&hsb0[j * HSS + f4]) =
                __ldg(reinterpret_cast<const float4*>(&hbase[(size_t)j * NF + f4]));
        }
        __syncthreads();   // att + chunk 0 visible

        // Phase C: 4 f-passes; pass p computes from buf (p&1) while staging
        // pass p+1 into buf ((p+1)&1). One sync per pass.
        float* ob = out + (size_t)((q * NS + s) * NL) * NF;

        #pragma unroll
        for (int p = 0; p < 4; p++) {
            float* cur = (p & 1) ? hsb1 : hsb0;
            float* nxt = (p & 1) ? hsb0 : hsb1;

            if (p < 3) {   // stage next chunk (LDG latency hides behind compute below)
                #pragma unroll
                for (int e = t; e < NL * 64 / 4; e += 256) {
                    int j = e >> 4;
                    int f4 = (e & 15) * 4;
                    *reinterpret_cast<float4*>(&nxt[j * HSS + f4]) =
                        __ldg(reinterpret_cast<const float4*>(
                            &hbase[(size_t)j * NF + 64 * (p + 1) + f4]));
                }
            }

            float d[4][4];
            #pragma unroll
            for (int nt = 0; nt < 4; nt++)
                #pragma unroll
                for (int e = 0; e < 4; e++) d[nt][e] = 0.f;

            const float* aH = attH + (size_t)(m0 + gid) * ATS;

            #pragma unroll
            for (int k0 = 0; k0 < NL; k0 += 8) {
                unsigned ah0 = __float_as_uint(aH[k0 + tig]);
                unsigned ah1 = __float_as_uint(aH[8 * ATS + k0 + tig]);
                unsigned ah2 = __float_as_uint(aH[k0 + tig + 4]);
                unsigned ah3 = __float_as_uint(aH[8 * ATS + k0 + tig + 4]);
                const float* hr0 = cur + (size_t)(k0 + tig) * HSS + nw + gid;
                const float* hr1 = cur + (size_t)(k0 + tig + 4) * HSS + nw + gid;
                #pragma unroll
                for (int nt = 0; nt < 4; nt++) {
                    unsigned b0 = __float_as_uint(hr0[8 * nt]);
                    unsigned b1 = __float_as_uint(hr1[8 * nt]);
                    mma_tf32(d[nt], ah0, ah1, ah2, ah3, b0, b1);
                }
            }

            #pragma unroll
            for (int nt = 0; nt < 4; nt++) {
                int col = 64 * p + nw + 8 * nt + 2 * tig;
                *reinterpret_cast<float2*>(&ob[(size_t)(m0 + gid) * NF + col]) =
                    make_float2(d[nt][0], d[nt][1]);
                *reinterpret_cast<float2*>(&ob[(size_t)(m0 + gid + 8) * NF + col]) =
                    make_float2(d[nt][2], d[nt][3]);
            }

            if (p == 3 && t == 0)   // prefetch next ticket; ATOMG hides in pass 3
                tslot[0] = __uint_as_float(atomicAdd(&g_ticket, 1u));
            __syncthreads();   // staging (p+1) visible; cur free; tslot published
        }
    }
}

extern "C" void kernel_launch(void* const* d_in, const int* in_sizes, int n_in,
                              void* d_out, int out_size) {
    const float* qs = (const float*)d_in[0];
    const float* hs = (const float*)d_in[1];
    const float* W  = (const float*)d_in[2];
    const float* b  = (const float*)d_in[3];
    float* out = (float*)d_out;

    const int smem_attn = 13572 * (int)sizeof(float);  // 54288 B
    cudaFuncSetAttribute(k_attn, cudaFuncAttributeMaxDynamicSharedMemorySize, smem_attn);

    k_project<<<(NQ + NS) * 8, 128>>>(qs, hs, W, b);
    k_attn<<<148 * 3, 256, smem_attn>>>(out);
}